// round 5
// baseline (speedup 1.0000x reference)
#include <cuda_runtime.h>
#include <math.h>
#include <stdint.h>

// Problem constants
#define BB 4
#define LL 2048
#define DD 1024
#define EE 8
#define HH 4096
#define TT 8192          // B*L tokens
#define TWOD 2048
#define EPSV 1e-6f

// GEMM tiling
#define BMq 128
#define BNq 128
#define BKq 16
#define AS_STRIDE 20     // BK + 4 pad (conflict-free for A frag reads)
#define BS_STRIDE 136    // BN + 8 pad (conflict-free for B frag reads)

// ---------------- device scratch (allocation-free rule: __device__ globals) ---
__device__ float g_cond[BB * TWOD];                       // (B, 2D)
__device__ float g_t[(size_t)TT * DD];                    // xn tokens (T, D)
__device__ float g_hs[(size_t)TT * HH];                   // shared expert hidden
__device__ float g_hr[(size_t)2 * TT * HH];               // routed hidden, row = pair id
__device__ int   g_cnt[EE];                               // per-expert token counts
__device__ int   g_list[EE * TT];                         // per-expert pair-id lists
__device__ float g_pairw[2 * TT];                         // combine weight per pair

// ---------------- helpers ----------------------------------------------------
__device__ __forceinline__ unsigned f2tf(float f) {
    unsigned u;
    asm("cvt.rna.tf32.f32 %0, %1;" : "=r"(u) : "f"(f));
    return u;
}

__device__ __forceinline__ float4 tf4(float4 v) {
    float4 o;
    o.x = __uint_as_float(f2tf(v.x));
    o.y = __uint_as_float(f2tf(v.y));
    o.z = __uint_as_float(f2tf(v.z));
    o.w = __uint_as_float(f2tf(v.w));
    return o;
}

__device__ __forceinline__ float geluf(float v) {
    // jax.nn.gelu default: tanh approximation
    float u = 0.7978845608028654f * (v + 0.044715f * v * v * v);
    return 0.5f * v * (1.0f + tanhf(u));
}

__device__ __forceinline__ void mma_tf32(float* c, const unsigned* a, const unsigned* b) {
    asm volatile(
        "mma.sync.aligned.m16n8k8.row.col.f32.tf32.tf32.f32 "
        "{%0,%1,%2,%3}, {%4,%5,%6,%7}, {%8,%9}, {%0,%1,%2,%3};\n"
        : "+f"(c[0]), "+f"(c[1]), "+f"(c[2]), "+f"(c[3])
        : "r"(a[0]), "r"(a[1]), "r"(a[2]), "r"(a[3]), "r"(b[0]), "r"(b[1]));
}

// ---------------- kernel: zero routing counters ------------------------------
__global__ void init_kernel() {
    if (threadIdx.x < EE) g_cnt[threadIdx.x] = 0;
}

// ---------------- kernel: cond = silu(time_c) @ ada_w + ada_b ----------------
__global__ void cond_kernel(const float* __restrict__ time_c,
                            const float* __restrict__ ada_w,
                            const float* __restrict__ ada_b) {
    __shared__ float s[DD];
    int b = blockIdx.y;
    for (int i = threadIdx.x; i < DD; i += blockDim.x) {
        float v = time_c[b * DD + i];
        s[i] = v / (1.0f + expf(-v));
    }
    __syncthreads();
    int col = blockIdx.x * 256 + threadIdx.x;  // 0..2047
    float acc = 0.0f;
#pragma unroll 4
    for (int r = 0; r < DD; r++) acc += s[r] * ada_w[r * TWOD + col];
    g_cond[b * TWOD + col] = acc + ada_b[col];
}

// ---------------- kernel: LN + modulate + router (one token per block) -------
__global__ void ln_route_kernel(const float* __restrict__ x,
                                const float* __restrict__ gate_w) {
    int tok = blockIdx.x;
    int b = tok / LL;
    const float* xr = x + (size_t)tok * DD;

    __shared__ float sx[DD];
    __shared__ float sred[16];
    __shared__ float smv[2];
    __shared__ float slog[EE];

    int tid = threadIdx.x, lane = tid & 31, w = tid >> 5;

    float lsum = 0.0f, lsq = 0.0f;
    for (int i = tid; i < DD; i += 256) {
        float v = xr[i];
        sx[i] = v;
        lsum += v;
        lsq += v * v;
    }
#pragma unroll
    for (int o = 16; o > 0; o >>= 1) {
        lsum += __shfl_down_sync(0xffffffffu, lsum, o);
        lsq  += __shfl_down_sync(0xffffffffu, lsq, o);
    }
    if (lane == 0) { sred[w] = lsum; sred[8 + w] = lsq; }
    __syncthreads();
    if (tid == 0) {
        float s = 0.0f, q = 0.0f;
        for (int i = 0; i < 8; i++) { s += sred[i]; q += sred[8 + i]; }
        float mean = s / (float)DD;
        float var = q / (float)DD - mean * mean;
        smv[0] = mean;
        smv[1] = rsqrtf(var + EPSV);
    }
    __syncthreads();
    float mean = smv[0], rstd = smv[1];
    const float* shiftp = g_cond + b * TWOD;
    const float* scalep = shiftp + DD;
    for (int i = tid; i < DD; i += 256) {
        float ln = (sx[i] - mean) * rstd;
        float xn = ln * (1.0f + scalep[i]) + shiftp[i];
        sx[i] = xn;
        g_t[(size_t)tok * DD + i] = xn;
    }
    __syncthreads();

    // router logits: warp w computes expert w (E=8 == number of warps)
    float acc = 0.0f;
    for (int r = lane; r < DD; r += 32) acc += sx[r] * gate_w[r * EE + w];
#pragma unroll
    for (int o = 16; o > 0; o >>= 1) acc += __shfl_down_sync(0xffffffffu, acc, o);
    if (lane == 0) slog[w] = acc;
    __syncthreads();

    if (tid == 0) {
        float m = slog[0];
        for (int e = 1; e < EE; e++) m = fmaxf(m, slog[e]);
        float p[EE];
        for (int e = 0; e < EE; e++) p[e] = expf(slog[e] - m);
        // top-2 (first occurrence on ties, matching jax top_k)
        int i0 = 0; float v0 = p[0];
        for (int e = 1; e < EE; e++) if (p[e] > v0) { v0 = p[e]; i0 = e; }
        int i1 = -1; float v1 = -1.0f;
        for (int e = 0; e < EE; e++) if (e != i0 && p[e] > v1) { v1 = p[e]; i1 = e; }
        float inv = 1.0f / (v0 + v1);
        float w0 = v0 * inv, w1 = v1 * inv;  // softmax denom cancels in renorm
        int pos0 = atomicAdd(&g_cnt[i0], 1);
        g_list[i0 * TT + pos0] = tok * 2;
        int pos1 = atomicAdd(&g_cnt[i1], 1);
        g_list[i1 * TT + pos1] = tok * 2 + 1;
        g_pairw[tok * 2] = w0;
        g_pairw[tok * 2 + 1] = w1;
    }
}

// ---------------- tf32 tensor-core GEMM --------------------------------------
// C(MxN) = gather(A)(MxK) @ W(KxN), epilogues:
//   FFN1: Out[orow] = gelu(acc + bias)           (store hidden)
//   FFN2 shared: Out[orow] = xres + acc + bias   (initialize output w/ residual)
//   FFN2 routed: atomicAdd(Out[orow], w*(acc+bias))
template <bool ROUTED, bool FFN2>
__global__ __launch_bounds__(256)
void gemm_kernel(const float* __restrict__ Abase,
                 const float* __restrict__ Wbase,
                 const float* __restrict__ biasbase,
                 const float* __restrict__ xres,
                 float* __restrict__ Out,
                 int Kdim, int Ndim) {
    int e = ROUTED ? blockIdx.z : 0;
    int n_rows = ROUTED ? g_cnt[e] : TT;
    int m0 = blockIdx.y * BMq;
    if (ROUTED && m0 >= n_rows) return;
    int n0 = blockIdx.x * BNq;
    const float* W = Wbase + (ROUTED ? (size_t)e * Kdim * Ndim : 0);
    const float* bias = biasbase + (ROUTED ? (size_t)e * Ndim : 0);

    __shared__ float As[2][BMq * AS_STRIDE];
    __shared__ float Bs[2][BKq * BS_STRIDE];
    __shared__ int srow[BMq];
    __shared__ int sorow[BMq];
    __shared__ float swt[BMq];

    int tid = threadIdx.x;
    if (tid < BMq) {
        int i = m0 + tid;
        int arow, orow;
        float wv = 1.0f;
        if (ROUTED) {
            bool valid = i < n_rows;
            int pair = valid ? g_list[e * TT + i] : 0;
            if (!FFN2) { arow = pair >> 1; orow = pair; }
            else       { arow = pair;      orow = pair >> 1; wv = g_pairw[pair]; }
            if (!valid) { arow = -1; orow = -1; }
        } else {
            arow = i; orow = i;
        }
        srow[tid] = arow;
        sorow[tid] = orow;
        swt[tid] = wv;
    }
    __syncthreads();

    // global->reg load mapping (512 float4 per tile, 2 per thread)
    int a_r0 = tid >> 2, a_c = (tid & 3) * 4;
    int a_r1 = a_r0 + 64;
    int b_r0 = tid >> 5, b_c = (tid & 31) * 4;
    int b_r1 = b_r0 + 8;

    int wid = tid >> 5, lane = tid & 31;
    int wm = wid & 3, wn = wid >> 2;   // warp tile 32(m) x 64(n)
    int lrow = lane >> 2, lcol = lane & 3;

    float acc[2][8][4];
#pragma unroll
    for (int a = 0; a < 2; a++)
#pragma unroll
        for (int bq = 0; bq < 8; bq++)
#pragma unroll
            for (int c = 0; c < 4; c++) acc[a][bq][c] = 0.0f;

    int NK = Kdim / BKq;
    float4 ra0, ra1, rb0, rb1;

    // prologue: load k-tile 0
    {
        int k0 = 0;
        int r = srow[a_r0];
        ra0 = (r >= 0) ? *(const float4*)(Abase + (size_t)r * Kdim + k0 + a_c)
                       : make_float4(0.f, 0.f, 0.f, 0.f);
        r = srow[a_r1];
        ra1 = (r >= 0) ? *(const float4*)(Abase + (size_t)r * Kdim + k0 + a_c)
                       : make_float4(0.f, 0.f, 0.f, 0.f);
        rb0 = *(const float4*)(W + (size_t)(k0 + b_r0) * Ndim + n0 + b_c);
        rb1 = *(const float4*)(W + (size_t)(k0 + b_r1) * Ndim + n0 + b_c);
        *(float4*)&As[0][a_r0 * AS_STRIDE + a_c] = tf4(ra0);
        *(float4*)&As[0][a_r1 * AS_STRIDE + a_c] = tf4(ra1);
        *(float4*)&Bs[0][b_r0 * BS_STRIDE + b_c] = tf4(rb0);
        *(float4*)&Bs[0][b_r1 * BS_STRIDE + b_c] = tf4(rb1);
    }
    __syncthreads();

    for (int kt = 0; kt < NK; kt++) {
        int buf = kt & 1;
        if (kt + 1 < NK) {
            int k0 = (kt + 1) * BKq;
            int r = srow[a_r0];
            ra0 = (r >= 0) ? *(const float4*)(Abase + (size_t)r * Kdim + k0 + a_c)
                           : make_float4(0.f, 0.f, 0.f, 0.f);
            r = srow[a_r1];
            ra1 = (r >= 0) ? *(const float4*)(Abase + (size_t)r * Kdim + k0 + a_c)
                           : make_float4(0.f, 0.f, 0.f, 0.f);
            rb0 = *(const float4*)(W + (size_t)(k0 + b_r0) * Ndim + n0 + b_c);
            rb1 = *(const float4*)(W + (size_t)(k0 + b_r1) * Ndim + n0 + b_c);
        }

        // compute on As[buf]/Bs[buf]
        {
            const float* as = As[buf];
            const float* bs = Bs[buf];
#pragma unroll
            for (int kk = 0; kk < 2; kk++) {
                int k8 = kk * 8;
                unsigned af[2][4];
#pragma unroll
                for (int tm = 0; tm < 2; tm++) {
                    const float* p = as + (wm * 32 + tm * 16 + lrow) * AS_STRIDE + k8 + lcol;
                    af[tm][0] = __float_as_uint(p[0]);
                    af[tm][1] = __float_as_uint(p[8 * AS_STRIDE]);
                    af[tm][2] = __float_as_uint(p[4]);
                    af[tm][3] = __float_as_uint(p[8 * AS_STRIDE + 4]);
                }
                unsigned bf[8][2];
#pragma unroll
                for (int tn = 0; tn < 8; tn++) {
                    const float* p = bs + (k8 + lcol) * BS_STRIDE + wn * 64 + tn * 8 + lrow;
                    bf[tn][0] = __float_as_uint(p[0]);
                    bf[tn][1] = __float_as_uint(p[4 * BS_STRIDE]);
                }
#pragma unroll
                for (int tm = 0; tm < 2; tm++)
#pragma unroll
                    for (int tn = 0; tn < 8; tn++)
                        mma_tf32(acc[tm][tn], af[tm], bf[tn]);
            }
        }

        if (kt + 1 < NK) {
            *(float4*)&As[buf ^ 1][a_r0 * AS_STRIDE + a_c] = tf4(ra0);
            *(float4*)&As[buf ^ 1][a_r1 * AS_STRIDE + a_c] = tf4(ra1);
            *(float4*)&Bs[buf ^ 1][b_r0 * BS_STRIDE + b_c] = tf4(rb0);
            *(float4*)&Bs[buf ^ 1][b_r1 * BS_STRIDE + b_c] = tf4(rb1);
            __syncthreads();
        }
    }

    // epilogue
#pragma unroll
    for (int tm = 0; tm < 2; tm++) {
#pragma unroll
        for (int rr = 0; rr < 2; rr++) {
            int li = wm * 32 + tm * 16 + rr * 8 + lrow;
            int orow = sorow[li];
            if (orow < 0) continue;
            float wv = swt[li];
#pragma unroll
            for (int tn = 0; tn < 8; tn++) {
                int col = n0 + wn * 64 + tn * 8 + lcol * 2;
                float c0 = acc[tm][tn][rr * 2 + 0];
                float c1 = acc[tm][tn][rr * 2 + 1];
                if (!FFN2) {
                    Out[(size_t)orow * Ndim + col]     = geluf(c0 + bias[col]);
                    Out[(size_t)orow * Ndim + col + 1] = geluf(c1 + bias[col + 1]);
                } else if (!ROUTED) {
                    size_t o = (size_t)orow * Ndim + col;
                    Out[o]     = xres[o]     + c0 + bias[col];
                    Out[o + 1] = xres[o + 1] + c1 + bias[col + 1];
                } else {
                    size_t o = (size_t)orow * Ndim + col;
                    atomicAdd(&Out[o],     wv * (c0 + bias[col]));
                    atomicAdd(&Out[o + 1], wv * (c1 + bias[col + 1]));
                }
            }
        }
    }
}

// ---------------- launch -----------------------------------------------------
extern "C" void kernel_launch(void* const* d_in, const int* in_sizes, int n_in,
                              void* d_out, int out_size) {
    const float* x      = (const float*)d_in[0];
    const float* time_c = (const float*)d_in[1];
    const float* ada_w  = (const float*)d_in[2];
    const float* ada_b  = (const float*)d_in[3];
    const float* gate_w = (const float*)d_in[4];
    const float* w1     = (const float*)d_in[5];
    const float* b1     = (const float*)d_in[6];
    const float* w2     = (const float*)d_in[7];
    const float* b2     = (const float*)d_in[8];
    const float* sw1    = (const float*)d_in[9];
    const float* sb1    = (const float*)d_in[10];
    const float* sw2    = (const float*)d_in[11];
    const float* sb2    = (const float*)d_in[12];
    float* out = (float*)d_out;

    float *p_t = nullptr, *p_hs = nullptr, *p_hr = nullptr;
    cudaGetSymbolAddress((void**)&p_t, g_t);
    cudaGetSymbolAddress((void**)&p_hs, g_hs);
    cudaGetSymbolAddress((void**)&p_hr, g_hr);

    init_kernel<<<1, 32>>>();
    cond_kernel<<<dim3(TWOD / 256, BB), 256>>>(time_c, ada_w, ada_b);
    ln_route_kernel<<<TT, 256>>>(x, gate_w);

    // shared FFN1: hs = gelu(t @ sw1 + sb1)
    gemm_kernel<false, false><<<dim3(HH / BNq, TT / BMq, 1), 256>>>(
        p_t, sw1, sb1, nullptr, p_hs, DD, HH);
    // routed FFN1: hr[pair] = gelu(t[tok] @ w1[e] + b1[e])
    gemm_kernel<true, false><<<dim3(HH / BNq, TT / BMq, EE), 256>>>(
        p_t, w1, b1, nullptr, p_hr, DD, HH);
    // shared FFN2 (+ residual): out = x + hs @ sw2 + sb2
    gemm_kernel<false, true><<<dim3(DD / BNq, TT / BMq, 1), 256>>>(
        p_hs, sw2, sb2, x, out, HH, DD);
    // routed FFN2: out[tok] += w * (hr[pair] @ w2[e] + b2[e])
    gemm_kernel<true, true><<<dim3(DD / BNq, TT / BMq, EE), 256>>>(
        p_hr, w2, b2, nullptr, out, HH, DD);
}